// round 4
// baseline (speedup 1.0000x reference)
#include <cuda_runtime.h>
#include <cstdint>

// Problem constants (from reference setup_inputs)
#define B_  8
#define N_  131072            // 2^17
#define M_  (B_ * N_)         // 1048576 points
#define C_  76
#define PTS 128               // points per decode block

// custom onesweep sort config
#define STH   256             // threads per sort tile
#define SIT   16              // items per thread
#define STILE (STH * SIT)     // 4096 items per tile
#define SNT   (M_ / STILE)    // 256 tiles per pass

// rank+gather tiling
#define GTH    256
#define GIT    8
#define GTILE  (GTH * GIT)    // 2048
#define NTILES (M_ / GTILE)   // 512

#define FLAG_AGG (1u << 30)
#define FLAG_INC (2u << 30)
#define VALMASK  ((1u << 30) - 1u)

// ---------------- device scratch (no allocation allowed) ----------------
struct State {                                   // zeroed once per launch
    unsigned int counters[8];                    // [0..3]=sort passes, [4]=rank_gather
    unsigned int hist[4][256];
    unsigned int sort_status[4][SNT][256];       // 1 MB lookback state
    unsigned int rg_status[NTILES][8];
};
__device__ State        g_state;
__device__ unsigned int g_bin_excl[4][256];      // fully overwritten each launch
__device__ float        g_props[(size_t)M_ * 8]; // 32 MB
__device__ unsigned int g_keys[M_];
__device__ unsigned int g_keys_alt[M_];
__device__ unsigned int g_vals[M_];
__device__ unsigned int g_vals_alt[M_];

// ---------------- decode: thread per point, smem-staged ----------------
// reg layout per point (76 floats):
//  [0:12) x bins  [12:24) z bins  [24:36) x res  [36:48) z res
//  [48] y off     [49:61) ry bins [61:73) ry res [73:76) hwl
__global__ __launch_bounds__(PTS) void decode_kernel(
    const float* __restrict__ scores,
    const float* __restrict__ reg,
    const float* __restrict__ xyz,
    const float* __restrict__ anchor)
{
    __shared__ float s[PTS * 77];
    __shared__ float sxyz[PTS * 3];

    const int tid  = threadIdx.x;
    const int base = blockIdx.x * PTS;

    const float* gsrc = reg + (size_t)base * C_;
    #pragma unroll
    for (int k = 0; k < C_; ++k) {
        const int i = tid + k * PTS;
        const int p = i / C_;
        const int c = i - p * C_;
        s[p * 77 + c] = gsrc[i];
    }
    #pragma unroll
    for (int k = 0; k < 3; ++k)
        sxyz[tid + k * PTS] = xyz[(size_t)base * 3 + tid + k * PTS];
    __syncthreads();

    const int    p = base + tid;
    const float* r = s + tid * 77;

    int xb = 0; float xv = r[0];
    #pragma unroll
    for (int j = 1; j < 12; ++j) { float v = r[j];      if (v > xv) { xv = v; xb = j; } }
    int zb = 0; float zv = r[12];
    #pragma unroll
    for (int j = 1; j < 12; ++j) { float v = r[12 + j]; if (v > zv) { zv = v; zb = j; } }
    int rb = 0; float rv = r[49];
    #pragma unroll
    for (int j = 1; j < 12; ++j) { float v = r[49 + j]; if (v > rv) { rv = v; rb = j; } }

    const float x_res  = r[24 + xb];
    const float z_res  = r[36 + zb];
    const float y_off  = r[48];
    const float ry_res = r[61 + rb];
    const float hr = r[73], wr = r[74], lr = r[75];

    const float roi0 = sxyz[tid * 3 + 0];
    const float roi1 = sxyz[tid * 3 + 1];
    const float roi2 = sxyz[tid * 3 + 2];

    const float an0 = __ldg(anchor);
    const float an1 = __ldg(anchor + 1);
    const float an2 = __ldg(anchor + 2);

    const float LOC_BIN = 0.5f, HALF = 0.25f, SCOPE = 3.0f;
    const float pos_x = (float)xb * LOC_BIN + HALF - SCOPE + x_res * LOC_BIN;
    const float pos_z = (float)zb * LOC_BIN + HALF - SCOPE + z_res * LOC_BIN;
    const float pos_y = roi1 + y_off;

    const float TWO_PI = 6.28318530717958647692f;
    const float PI_    = 3.14159265358979323846f;
    const float APC    = 0.52359877559829887308f;   // 2*pi/12
    float ry = (float)rb * APC + ry_res * (APC * 0.5f);
    ry = fmodf(ry, TWO_PI);
    if (ry < 0.f) ry += TWO_PI;
    if (ry > PI_) ry -= TWO_PI;

    const float h_ = hr * an0 + an0;
    const float w_ = wr * an1 + an1;
    const float l_ = lr * an2 + an2;

    const float px = pos_x + roi0;
    const float pz = pos_z + roi2;
    const float py = pos_y + h_ * 0.5f;

    const float sc = __ldg(scores + p);

    float4* pp = (float4*)g_props;
    pp[2 * (size_t)p]     = make_float4(px, py, pz, h_);
    pp[2 * (size_t)p + 1] = make_float4(w_, l_, ry, sc);

    unsigned int u = __float_as_uint(sc);
    u ^= (u & 0x80000000u) ? 0xFFFFFFFFu : 0x80000000u;
    g_keys[p] = ~u;              // ascending == descending score
    g_vals[p] = (unsigned int)p;
}

// ---------------- histogram: all 4 pass histograms in one read ----------------
__global__ __launch_bounds__(256) void hist_kernel(const unsigned int* __restrict__ keys)
{
    __shared__ unsigned int h[4][256];
    const int tid = threadIdx.x;
    #pragma unroll
    for (int p = 0; p < 4; ++p) h[p][tid] = 0;
    __syncthreads();
    const size_t base = (size_t)blockIdx.x * 256 * 8;
    #pragma unroll
    for (int k = 0; k < 8; ++k) {
        const unsigned int key = keys[base + k * 256 + tid];
        atomicAdd(&h[0][key & 255u], 1u);
        atomicAdd(&h[1][(key >> 8) & 255u], 1u);
        atomicAdd(&h[2][(key >> 16) & 255u], 1u);
        atomicAdd(&h[3][key >> 24], 1u);
    }
    __syncthreads();
    #pragma unroll
    for (int p = 0; p < 4; ++p) atomicAdd(&g_state.hist[p][tid], h[p][tid]);
}

// ---------------- exclusive scan of the 4 histograms (1 block) ----------------
__global__ __launch_bounds__(256) void scan_kernel()
{
    __shared__ unsigned int s[512];
    const int tid = threadIdx.x;
    for (int p = 0; p < 4; ++p) {
        const unsigned int x = g_state.hist[p][tid];
        s[tid] = 0; s[256 + tid] = x;
        __syncthreads();
        #pragma unroll
        for (int d = 1; d < 256; d <<= 1) {
            const unsigned int v = s[256 + tid] + s[256 + tid - d];
            __syncthreads();
            s[256 + tid] = v;
            __syncthreads();
        }
        g_bin_excl[p][tid] = s[256 + tid] - x;   // exclusive
        __syncthreads();
    }
}

// ---------------- custom onesweep pass (stable, pairs) ----------------
template<int SHIFT, int PASS, bool WRITE_KEYS>
__global__ __launch_bounds__(STH) void onesweep_pass(
    const unsigned int* __restrict__ keys_in,
    const unsigned int* __restrict__ vals_in,
    unsigned int* __restrict__ keys_out,
    unsigned int* __restrict__ vals_out)
{
    __shared__ unsigned int s_keys[STILE];       // 16 KB
    __shared__ unsigned int s_vals[STILE];       // 16 KB
    __shared__ unsigned int s_warpcnt[8][256];   // 8 KB
    __shared__ unsigned int s_base[256];
    __shared__ unsigned int s_tile_excl[256];
    __shared__ unsigned int s_gbase[256];
    __shared__ unsigned int s_scan[512];
    __shared__ unsigned int s_tileid;

    const int tid = threadIdx.x, lane = tid & 31, warp = tid >> 5;
    const unsigned FULL = 0xffffffffu;

    if (tid == 0) s_tileid = atomicAdd(&g_state.counters[PASS], 1u);
    s_base[tid] = 0;
    __syncthreads();
    const int    tile  = (int)s_tileid;
    const size_t ibase = (size_t)tile * STILE;

    unsigned int key[SIT], val[SIT], rnk[SIT];
    #pragma unroll
    for (int k = 0; k < SIT; ++k) {
        key[k] = keys_in[ibase + k * STH + tid];   // striped == ascending order
        val[k] = vals_in[ibase + k * STH + tid];
    }

    // stable intra-tile ranking, slice by slice
    #pragma unroll
    for (int k = 0; k < SIT; ++k) {
        unsigned int* wf = &s_warpcnt[0][0];
        #pragma unroll
        for (int i = 0; i < 8; ++i) wf[tid + i * 256] = 0;
        __syncthreads();
        const unsigned int d = (key[k] >> SHIFT) & 255u;
        const unsigned int peers = __match_any_sync(FULL, d);
        if (lane == (int)(__ffs(peers) - 1)) s_warpcnt[warp][d] = __popc(peers);
        __syncthreads();
        unsigned int off = s_base[d];
        #pragma unroll
        for (int w = 0; w < 8; ++w) if (w < warp) off += s_warpcnt[w][d];
        rnk[k] = off + __popc(peers & ((1u << lane) - 1u));
        __syncthreads();
        unsigned int t = 0;
        #pragma unroll
        for (int w = 0; w < 8; ++w) t += s_warpcnt[w][tid];
        s_base[tid] += t;
        __syncthreads();
    }

    // totals per digit now in s_base; publish aggregate immediately
    const unsigned int agg = s_base[tid];
    if (tile == 0)
        ((volatile unsigned int*)g_state.sort_status[PASS][0])[tid] = FLAG_INC | agg;
    else
        ((volatile unsigned int*)g_state.sort_status[PASS][tile])[tid] = FLAG_AGG | agg;
    __threadfence();

    // intra-tile exclusive scan of digit totals
    s_scan[tid] = 0; s_scan[256 + tid] = agg;
    __syncthreads();
    #pragma unroll
    for (int d = 1; d < 256; d <<= 1) {
        const unsigned int v = s_scan[256 + tid] + s_scan[256 + tid - d];
        __syncthreads();
        s_scan[256 + tid] = v;
        __syncthreads();
    }
    s_tile_excl[tid] = s_scan[256 + tid] - agg;
    __syncthreads();

    // stage into smem grouped by digit (digit recomputed from key: saves regs)
    #pragma unroll
    for (int k = 0; k < SIT; ++k) {
        const unsigned int d   = (key[k] >> SHIFT) & 255u;
        const unsigned int pos = s_tile_excl[d] + rnk[k];
        s_keys[pos] = key[k];
        s_vals[pos] = val[k];
    }

    // decoupled lookback: thread tid owns bin tid
    unsigned int excl = 0;
    if (tile > 0) {
        volatile unsigned int* col = &g_state.sort_status[PASS][0][tid];
        int t = tile - 1;
        while (true) {
            unsigned int stv;
            do { stv = col[(size_t)t * 256]; } while (stv == 0u);
            excl += stv & VALMASK;
            if (stv & FLAG_INC) break;
            --t;
        }
        ((volatile unsigned int*)g_state.sort_status[PASS][tile])[tid] = FLAG_INC | (excl + agg);
        __threadfence();
    }
    s_gbase[tid] = g_bin_excl[PASS][tid] + excl - s_tile_excl[tid];
    __syncthreads();

    // coalesced global scatter: consecutive j within a digit -> consecutive dest
    #pragma unroll
    for (int k = 0; k < SIT; ++k) {
        const int j = k * STH + tid;
        const unsigned int kk = s_keys[j];
        const unsigned int d  = (kk >> SHIFT) & 255u;
        const unsigned int dest = s_gbase[d] + j;
        if (WRITE_KEYS) keys_out[dest] = kk;
        vals_out[dest] = s_vals[j];
    }
}

// ------- fused stable 8-way rank (decoupled lookback) + gather/scatter -------
__global__ __launch_bounds__(GTH) void rank_gather_kernel(
    const unsigned int* __restrict__ sorted_vals,
    float4* __restrict__ out)
{
    __shared__ unsigned int s_warpcnt[8][8];
    __shared__ unsigned int s_base[8];
    __shared__ unsigned int s_excl[8];
    __shared__ unsigned int s_tile;

    const int tid  = threadIdx.x;
    const int lane = tid & 31;
    const int warp = tid >> 5;
    const unsigned FULL = 0xffffffffu;

    if (tid == 0) s_tile = atomicAdd(&g_state.counters[4], 1u);
    if (tid < 8)  s_base[tid] = 0;
    __syncthreads();
    const int tile  = (int)s_tile;
    const int ibase = tile * GTILE;

    unsigned int v[GIT]; int row[GIT]; unsigned int rk[GIT];
    #pragma unroll
    for (int k = 0; k < GIT; ++k) {
        v[k]   = __ldg(sorted_vals + ibase + k * GTH + tid);
        row[k] = (int)(v[k] >> 17);
    }

    #pragma unroll
    for (int k = 0; k < GIT; ++k) {
        unsigned int bal[8];
        #pragma unroll
        for (int r = 0; r < 8; ++r) bal[r] = __ballot_sync(FULL, row[k] == r);
        const unsigned int lt = (1u << lane) - 1u;
        unsigned int rank = __popc(bal[row[k]] & lt);
        if (lane < 8) s_warpcnt[warp][lane] = __popc(bal[lane]);
        __syncthreads();
        unsigned int off = s_base[row[k]];
        #pragma unroll
        for (int w = 0; w < 8; ++w)
            if (w < warp) off += s_warpcnt[w][row[k]];
        rk[k] = off + rank;
        __syncthreads();
        if (tid < 8) {
            unsigned int t = 0;
            #pragma unroll
            for (int w = 0; w < 8; ++w) t += s_warpcnt[w][tid];
            s_base[tid] += t;
        }
        __syncthreads();
    }

    if (tid < 8) {
        const unsigned int agg = s_base[tid];
        volatile unsigned int* st_col = &g_state.rg_status[0][tid];
        if (tile == 0) {
            g_state.rg_status[0][tid] = FLAG_INC | agg;
            __threadfence();
            s_excl[tid] = 0;
        } else {
            g_state.rg_status[tile][tid] = FLAG_AGG | agg;
            __threadfence();
            unsigned int excl = 0;
            int t = tile - 1;
            while (true) {
                unsigned int stv;
                do { stv = st_col[(size_t)t * 8]; } while (stv == 0u);
                excl += stv & VALMASK;
                if (stv & FLAG_INC) break;
                --t;
            }
            g_state.rg_status[tile][tid] = FLAG_INC | (excl + agg);
            __threadfence();
            s_excl[tid] = excl;
        }
    }
    __syncthreads();

    const float4* pp = (const float4*)g_props;
    #pragma unroll
    for (int k = 0; k < GIT; ++k) {
        const unsigned int src = v[k];
        const unsigned int dst = (unsigned int)row[k] * N_ + s_excl[row[k]] + rk[k];
        out[2 * (size_t)dst]     = __ldg(&pp[2 * (size_t)src]);
        out[2 * (size_t)dst + 1] = __ldg(&pp[2 * (size_t)src + 1]);
    }
}

// ---------------- launch ----------------
extern "C" void kernel_launch(void* const* d_in, const int* in_sizes, int n_in,
                              void* d_out, int out_size)
{
    const float* scores = (const float*)d_in[0];
    const float* reg    = (const float*)d_in[1];
    const float* xyz    = (const float*)d_in[2];
    const float* anchor = (const float*)d_in[3];

    void* pst; cudaGetSymbolAddress(&pst, g_state);
    cudaMemsetAsync(pst, 0, sizeof(State));

    decode_kernel<<<M_ / PTS, PTS>>>(scores, reg, xyz, anchor);

    void *pk, *pka, *pv, *pva;
    cudaGetSymbolAddress(&pk,  g_keys);
    cudaGetSymbolAddress(&pka, g_keys_alt);
    cudaGetSymbolAddress(&pv,  g_vals);
    cudaGetSymbolAddress(&pva, g_vals_alt);

    hist_kernel<<<M_ / (256 * 8), 256>>>((const unsigned int*)pk);
    scan_kernel<<<1, 256>>>();

    onesweep_pass< 0, 0, true ><<<SNT, STH>>>((const unsigned int*)pk,  (const unsigned int*)pv,
                                              (unsigned int*)pka, (unsigned int*)pva);
    onesweep_pass< 8, 1, true ><<<SNT, STH>>>((const unsigned int*)pka, (const unsigned int*)pva,
                                              (unsigned int*)pk,  (unsigned int*)pv);
    onesweep_pass<16, 2, true ><<<SNT, STH>>>((const unsigned int*)pk,  (const unsigned int*)pv,
                                              (unsigned int*)pka, (unsigned int*)pva);
    onesweep_pass<24, 3, false><<<SNT, STH>>>((const unsigned int*)pka, (const unsigned int*)pva,
                                              (unsigned int*)pk,  (unsigned int*)pv);

    rank_gather_kernel<<<NTILES, GTH>>>((const unsigned int*)pv, (float4*)d_out);
}

// round 5
// speedup vs baseline: 1.0451x; 1.0451x over previous
#include <cuda_runtime.h>
#include <cstdint>

// Problem constants (from reference setup_inputs)
#define B_  8
#define N_  131072            // 2^17
#define M_  (B_ * N_)         // 1048576 points
#define C_  76
#define PTS 128               // points per decode block

// custom onesweep sort config
#define STH   256             // threads per sort tile (8 warps)
#define SIT   16              // items per thread
#define STILE (STH * SIT)     // 4096 items per tile
#define SNT   (M_ / STILE)    // 256 tiles per pass
#define WSEG  (32 * SIT)      // 512 contiguous items per warp

// rank+gather tiling
#define GTH    256
#define GIT    8
#define GTILE  (GTH * GIT)    // 2048
#define NTILES (M_ / GTILE)   // 512

#define FLAG_AGG (1u << 30)
#define FLAG_INC (2u << 30)
#define VALMASK  ((1u << 30) - 1u)

// ---------------- device scratch (no allocation allowed) ----------------
struct State {                                   // zeroed once per launch
    unsigned int counters[8];                    // [0..3]=sort passes, [4]=rank_gather
    unsigned int hist[4][256];
    unsigned int sort_status[4][SNT][256];       // 1 MB lookback state
    unsigned int rg_status[NTILES][8];
};
__device__ State        g_state;
__device__ unsigned int g_bin_excl[4][256];      // fully overwritten each launch
__device__ float        g_props[(size_t)M_ * 8]; // 32 MB
__device__ unsigned int g_keys[M_];
__device__ unsigned int g_keys_alt[M_];
__device__ unsigned int g_vals[M_];
__device__ unsigned int g_vals_alt[M_];

// ---------------- decode: thread per point, smem-staged ----------------
// reg layout per point (76 floats):
//  [0:12) x bins  [12:24) z bins  [24:36) x res  [36:48) z res
//  [48] y off     [49:61) ry bins [61:73) ry res [73:76) hwl
__global__ __launch_bounds__(PTS) void decode_kernel(
    const float* __restrict__ scores,
    const float* __restrict__ reg,
    const float* __restrict__ xyz,
    const float* __restrict__ anchor)
{
    __shared__ float s[PTS * 77];
    __shared__ float sxyz[PTS * 3];

    const int tid  = threadIdx.x;
    const int base = blockIdx.x * PTS;

    const float* gsrc = reg + (size_t)base * C_;
    #pragma unroll
    for (int k = 0; k < C_; ++k) {
        const int i = tid + k * PTS;
        const int p = i / C_;
        const int c = i - p * C_;
        s[p * 77 + c] = gsrc[i];
    }
    #pragma unroll
    for (int k = 0; k < 3; ++k)
        sxyz[tid + k * PTS] = xyz[(size_t)base * 3 + tid + k * PTS];
    __syncthreads();

    const int    p = base + tid;
    const float* r = s + tid * 77;

    int xb = 0; float xv = r[0];
    #pragma unroll
    for (int j = 1; j < 12; ++j) { float v = r[j];      if (v > xv) { xv = v; xb = j; } }
    int zb = 0; float zv = r[12];
    #pragma unroll
    for (int j = 1; j < 12; ++j) { float v = r[12 + j]; if (v > zv) { zv = v; zb = j; } }
    int rb = 0; float rv = r[49];
    #pragma unroll
    for (int j = 1; j < 12; ++j) { float v = r[49 + j]; if (v > rv) { rv = v; rb = j; } }

    const float x_res  = r[24 + xb];
    const float z_res  = r[36 + zb];
    const float y_off  = r[48];
    const float ry_res = r[61 + rb];
    const float hr = r[73], wr = r[74], lr = r[75];

    const float roi0 = sxyz[tid * 3 + 0];
    const float roi1 = sxyz[tid * 3 + 1];
    const float roi2 = sxyz[tid * 3 + 2];

    const float an0 = __ldg(anchor);
    const float an1 = __ldg(anchor + 1);
    const float an2 = __ldg(anchor + 2);

    const float LOC_BIN = 0.5f, HALF = 0.25f, SCOPE = 3.0f;
    const float pos_x = (float)xb * LOC_BIN + HALF - SCOPE + x_res * LOC_BIN;
    const float pos_z = (float)zb * LOC_BIN + HALF - SCOPE + z_res * LOC_BIN;
    const float pos_y = roi1 + y_off;

    const float TWO_PI = 6.28318530717958647692f;
    const float PI_    = 3.14159265358979323846f;
    const float APC    = 0.52359877559829887308f;   // 2*pi/12
    float ry = (float)rb * APC + ry_res * (APC * 0.5f);
    ry = fmodf(ry, TWO_PI);
    if (ry < 0.f) ry += TWO_PI;
    if (ry > PI_) ry -= TWO_PI;

    const float h_ = hr * an0 + an0;
    const float w_ = wr * an1 + an1;
    const float l_ = lr * an2 + an2;

    const float px = pos_x + roi0;
    const float pz = pos_z + roi2;
    const float py = pos_y + h_ * 0.5f;

    const float sc = __ldg(scores + p);

    float4* pp = (float4*)g_props;
    pp[2 * (size_t)p]     = make_float4(px, py, pz, h_);
    pp[2 * (size_t)p + 1] = make_float4(w_, l_, ry, sc);

    unsigned int u = __float_as_uint(sc);
    u ^= (u & 0x80000000u) ? 0xFFFFFFFFu : 0x80000000u;
    g_keys[p] = ~u;              // ascending == descending score
    g_vals[p] = (unsigned int)p;
}

// ---------------- histogram: all 4 pass histograms in one read ----------------
__global__ __launch_bounds__(256) void hist_kernel(const unsigned int* __restrict__ keys)
{
    __shared__ unsigned int h[4][256];
    const int tid = threadIdx.x;
    #pragma unroll
    for (int p = 0; p < 4; ++p) h[p][tid] = 0;
    __syncthreads();
    const size_t base = (size_t)blockIdx.x * 256 * 8;
    #pragma unroll
    for (int k = 0; k < 8; ++k) {
        const unsigned int key = keys[base + k * 256 + tid];
        atomicAdd(&h[0][key & 255u], 1u);
        atomicAdd(&h[1][(key >> 8) & 255u], 1u);
        atomicAdd(&h[2][(key >> 16) & 255u], 1u);
        atomicAdd(&h[3][key >> 24], 1u);
    }
    __syncthreads();
    #pragma unroll
    for (int p = 0; p < 4; ++p) atomicAdd(&g_state.hist[p][tid], h[p][tid]);
}

// ---------------- exclusive scan of the 4 histograms (1 block) ----------------
__global__ __launch_bounds__(256) void scan_kernel()
{
    __shared__ unsigned int s[512];
    const int tid = threadIdx.x;
    for (int p = 0; p < 4; ++p) {
        const unsigned int x = g_state.hist[p][tid];
        s[tid] = 0; s[256 + tid] = x;
        __syncthreads();
        #pragma unroll
        for (int d = 1; d < 256; d <<= 1) {
            const unsigned int v = s[256 + tid] + s[256 + tid - d];
            __syncthreads();
            s[256 + tid] = v;
            __syncthreads();
        }
        g_bin_excl[p][tid] = s[256 + tid] - x;   // exclusive
        __syncthreads();
    }
}

// ---------------- custom onesweep pass (stable, pairs) ----------------
// Warp-private ranking: warp w owns contiguous items [w*512, (w+1)*512) of the
// tile; slices of 32 (ascending lane == ascending j) keep stability. No block
// barriers inside the ranking loop.
template<int SHIFT, int PASS, bool WRITE_KEYS>
__global__ __launch_bounds__(STH) void onesweep_pass(
    const unsigned int* __restrict__ keys_in,
    const unsigned int* __restrict__ vals_in,
    unsigned int* __restrict__ keys_out,
    unsigned int* __restrict__ vals_out)
{
    __shared__ unsigned int s_keys[STILE];       // 16 KB
    __shared__ unsigned int s_vals[STILE];       // 16 KB
    __shared__ unsigned int s_wc[8][256];        // 8 KB: warp digit counts -> excl offsets
    __shared__ unsigned int s_tile_excl[256];
    __shared__ unsigned int s_gbase[256];
    __shared__ unsigned int s_scan[512];
    __shared__ unsigned int s_tileid;

    const int tid = threadIdx.x, lane = tid & 31, warp = tid >> 5;
    const unsigned FULL = 0xffffffffu;
    const unsigned lt   = (1u << lane) - 1u;

    if (tid == 0) s_tileid = atomicAdd(&g_state.counters[PASS], 1u);
    #pragma unroll
    for (int i = 0; i < 8; ++i) (&s_wc[0][0])[tid + i * 256] = 0;
    __syncthreads();
    const int    tile  = (int)s_tileid;
    const size_t ibase = (size_t)tile * STILE;
    const size_t wbase = ibase + (size_t)warp * WSEG;

    unsigned int key[SIT];
    unsigned short rnk[SIT];
    unsigned int* wc = s_wc[warp];

    // warp-private stable ranking (no __syncthreads in loop)
    #pragma unroll
    for (int k = 0; k < SIT; ++k) {
        key[k] = keys_in[wbase + k * 32 + lane];
        const unsigned int d     = (key[k] >> SHIFT) & 255u;
        const unsigned int peers = __match_any_sync(FULL, d);
        const unsigned int cnt   = wc[d];                 // peers hit same addr: broadcast
        rnk[k] = (unsigned short)(cnt + __popc(peers & lt));
        if ((peers >> lane) == 1u)                        // highest peer lane updates
            wc[d] = cnt + __popc(peers);
        __syncwarp();
    }
    __syncthreads();

    // per-digit cross-warp exclusive scan + digit totals (thread tid owns digit tid)
    unsigned int run = 0;
    #pragma unroll
    for (int w = 0; w < 8; ++w) {
        const unsigned int c = s_wc[w][tid];
        s_wc[w][tid] = run;                               // exclusive warp offset
        run += c;
    }
    const unsigned int agg = run;

    // publish aggregate early
    if (tile == 0)
        ((volatile unsigned int*)g_state.sort_status[PASS][0])[tid] = FLAG_INC | agg;
    else
        ((volatile unsigned int*)g_state.sort_status[PASS][tile])[tid] = FLAG_AGG | agg;
    __threadfence();

    // intra-tile exclusive scan of digit totals
    s_scan[tid] = 0; s_scan[256 + tid] = agg;
    __syncthreads();
    #pragma unroll
    for (int d = 1; d < 256; d <<= 1) {
        const unsigned int v = s_scan[256 + tid] + s_scan[256 + tid - d];
        __syncthreads();
        s_scan[256 + tid] = v;
        __syncthreads();
    }
    s_tile_excl[tid] = s_scan[256 + tid] - agg;
    __syncthreads();

    // stage into smem grouped by digit; fetch vals from gmem on the fly
    #pragma unroll
    for (int k = 0; k < SIT; ++k) {
        const unsigned int d   = (key[k] >> SHIFT) & 255u;
        const unsigned int pos = s_tile_excl[d] + s_wc[warp][d] + rnk[k];
        s_keys[pos] = key[k];
        s_vals[pos] = vals_in[wbase + k * 32 + lane];
    }

    // decoupled lookback: thread tid owns bin tid
    unsigned int excl = 0;
    if (tile > 0) {
        volatile unsigned int* col = &g_state.sort_status[PASS][0][tid];
        int t = tile - 1;
        while (true) {
            unsigned int stv;
            do { stv = col[(size_t)t * 256]; } while (stv == 0u);
            excl += stv & VALMASK;
            if (stv & FLAG_INC) break;
            --t;
        }
        ((volatile unsigned int*)g_state.sort_status[PASS][tile])[tid] = FLAG_INC | (excl + agg);
        __threadfence();
    }
    s_gbase[tid] = g_bin_excl[PASS][tid] + excl - s_tile_excl[tid];
    __syncthreads();

    // coalesced global scatter: consecutive j within a digit -> consecutive dest
    #pragma unroll
    for (int k = 0; k < SIT; ++k) {
        const int j = k * STH + tid;
        const unsigned int kk = s_keys[j];
        const unsigned int d  = (kk >> SHIFT) & 255u;
        const unsigned int dest = s_gbase[d] + j;
        if (WRITE_KEYS) keys_out[dest] = kk;
        vals_out[dest] = s_vals[j];
    }
}

// ------- fused stable 8-way rank (decoupled lookback) + gather/scatter -------
__global__ __launch_bounds__(GTH) void rank_gather_kernel(
    const unsigned int* __restrict__ sorted_vals,
    float4* __restrict__ out)
{
    __shared__ unsigned int s_warpcnt[8][8];
    __shared__ unsigned int s_base[8];
    __shared__ unsigned int s_excl[8];
    __shared__ unsigned int s_tile;

    const int tid  = threadIdx.x;
    const int lane = tid & 31;
    const int warp = tid >> 5;
    const unsigned FULL = 0xffffffffu;

    if (tid == 0) s_tile = atomicAdd(&g_state.counters[4], 1u);
    if (tid < 8)  s_base[tid] = 0;
    __syncthreads();
    const int tile  = (int)s_tile;
    const int ibase = tile * GTILE;

    unsigned int v[GIT]; int row[GIT]; unsigned int rk[GIT];
    #pragma unroll
    for (int k = 0; k < GIT; ++k) {
        v[k]   = __ldg(sorted_vals + ibase + k * GTH + tid);
        row[k] = (int)(v[k] >> 17);
    }

    #pragma unroll
    for (int k = 0; k < GIT; ++k) {
        unsigned int bal[8];
        #pragma unroll
        for (int r = 0; r < 8; ++r) bal[r] = __ballot_sync(FULL, row[k] == r);
        const unsigned int lt = (1u << lane) - 1u;
        unsigned int rank = __popc(bal[row[k]] & lt);
        if (lane < 8) s_warpcnt[warp][lane] = __popc(bal[lane]);
        __syncthreads();
        unsigned int off = s_base[row[k]];
        #pragma unroll
        for (int w = 0; w < 8; ++w)
            if (w < warp) off += s_warpcnt[w][row[k]];
        rk[k] = off + rank;
        __syncthreads();
        if (tid < 8) {
            unsigned int t = 0;
            #pragma unroll
            for (int w = 0; w < 8; ++w) t += s_warpcnt[w][tid];
            s_base[tid] += t;
        }
        __syncthreads();
    }

    if (tid < 8) {
        const unsigned int agg = s_base[tid];
        volatile unsigned int* st_col = &g_state.rg_status[0][tid];
        if (tile == 0) {
            g_state.rg_status[0][tid] = FLAG_INC | agg;
            __threadfence();
            s_excl[tid] = 0;
        } else {
            g_state.rg_status[tile][tid] = FLAG_AGG | agg;
            __threadfence();
            unsigned int excl = 0;
            int t = tile - 1;
            while (true) {
                unsigned int stv;
                do { stv = st_col[(size_t)t * 8]; } while (stv == 0u);
                excl += stv & VALMASK;
                if (stv & FLAG_INC) break;
                --t;
            }
            g_state.rg_status[tile][tid] = FLAG_INC | (excl + agg);
            __threadfence();
            s_excl[tid] = excl;
        }
    }
    __syncthreads();

    const float4* pp = (const float4*)g_props;
    #pragma unroll
    for (int k = 0; k < GIT; ++k) {
        const unsigned int src = v[k];
        const unsigned int dst = (unsigned int)row[k] * N_ + s_excl[row[k]] + rk[k];
        out[2 * (size_t)dst]     = __ldg(&pp[2 * (size_t)src]);
        out[2 * (size_t)dst + 1] = __ldg(&pp[2 * (size_t)src + 1]);
    }
}

// ---------------- launch ----------------
extern "C" void kernel_launch(void* const* d_in, const int* in_sizes, int n_in,
                              void* d_out, int out_size)
{
    const float* scores = (const float*)d_in[0];
    const float* reg    = (const float*)d_in[1];
    const float* xyz    = (const float*)d_in[2];
    const float* anchor = (const float*)d_in[3];

    void* pst; cudaGetSymbolAddress(&pst, g_state);
    cudaMemsetAsync(pst, 0, sizeof(State));

    decode_kernel<<<M_ / PTS, PTS>>>(scores, reg, xyz, anchor);

    void *pk, *pka, *pv, *pva;
    cudaGetSymbolAddress(&pk,  g_keys);
    cudaGetSymbolAddress(&pka, g_keys_alt);
    cudaGetSymbolAddress(&pv,  g_vals);
    cudaGetSymbolAddress(&pva, g_vals_alt);

    hist_kernel<<<M_ / (256 * 8), 256>>>((const unsigned int*)pk);
    scan_kernel<<<1, 256>>>();

    onesweep_pass< 0, 0, true ><<<SNT, STH>>>((const unsigned int*)pk,  (const unsigned int*)pv,
                                              (unsigned int*)pka, (unsigned int*)pva);
    onesweep_pass< 8, 1, true ><<<SNT, STH>>>((const unsigned int*)pka, (const unsigned int*)pva,
                                              (unsigned int*)pk,  (unsigned int*)pv);
    onesweep_pass<16, 2, true ><<<SNT, STH>>>((const unsigned int*)pk,  (const unsigned int*)pv,
                                              (unsigned int*)pka, (unsigned int*)pva);
    onesweep_pass<24, 3, false><<<SNT, STH>>>((const unsigned int*)pka, (const unsigned int*)pva,
                                              (unsigned int*)pk,  (unsigned int*)pv);

    rank_gather_kernel<<<NTILES, GTH>>>((const unsigned int*)pv, (float4*)d_out);
}

// round 6
// speedup vs baseline: 1.0883x; 1.0413x over previous
#include <cuda_runtime.h>
#include <cstdint>

// Problem constants (from reference setup_inputs)
#define B_  8
#define N_  131072            // 2^17
#define M_  (B_ * N_)         // 1048576 points
#define C_  76
#define PTS 128               // points per decode block

// custom onesweep sort config
#define STH   256             // threads per sort tile (8 warps)
#define SIT   16              // items per thread
#define STILE (STH * SIT)     // 4096 items per tile
#define SNT   (M_ / STILE)    // 256 tiles per pass
#define WSEG  (32 * SIT)      // 512 contiguous items per warp

// rank+gather tiling
#define GTH    256
#define GIT    8
#define GTILE  (GTH * GIT)    // 2048
#define NTILES (M_ / GTILE)   // 512
#define GSEG   (32 * GIT)     // 256 contiguous items per warp

#define FLAG_AGG (1u << 30)
#define FLAG_INC (2u << 30)
#define VALMASK  ((1u << 30) - 1u)
#define LBW      16           // lookback window (independent loads)

// ---------------- device scratch (no allocation allowed) ----------------
struct State {                                   // zeroed once per launch
    unsigned int counters[8];                    // [0..3]=sort passes, [4]=rank_gather
    unsigned int hist[4][256];
    unsigned int sort_status[4][SNT][256];       // 1 MB lookback state
    unsigned int rg_status[NTILES][8];
};
__device__ State        g_state;
__device__ unsigned int g_bin_excl[4][256];      // fully overwritten each launch
__device__ float        g_props[(size_t)M_ * 8]; // 32 MB
__device__ unsigned int g_keys[M_];
__device__ unsigned int g_keys_alt[M_];
__device__ unsigned int g_vals[M_];
__device__ unsigned int g_vals_alt[M_];

// ---------------- decode: thread per point, smem-staged ----------------
__global__ __launch_bounds__(PTS) void decode_kernel(
    const float* __restrict__ scores,
    const float* __restrict__ reg,
    const float* __restrict__ xyz,
    const float* __restrict__ anchor)
{
    __shared__ float s[PTS * 77];
    __shared__ float sxyz[PTS * 3];

    const int tid  = threadIdx.x;
    const int base = blockIdx.x * PTS;

    const float* gsrc = reg + (size_t)base * C_;
    #pragma unroll
    for (int k = 0; k < C_; ++k) {
        const int i = tid + k * PTS;
        const int p = i / C_;
        const int c = i - p * C_;
        s[p * 77 + c] = gsrc[i];
    }
    #pragma unroll
    for (int k = 0; k < 3; ++k)
        sxyz[tid + k * PTS] = xyz[(size_t)base * 3 + tid + k * PTS];
    __syncthreads();

    const int    p = base + tid;
    const float* r = s + tid * 77;

    int xb = 0; float xv = r[0];
    #pragma unroll
    for (int j = 1; j < 12; ++j) { float v = r[j];      if (v > xv) { xv = v; xb = j; } }
    int zb = 0; float zv = r[12];
    #pragma unroll
    for (int j = 1; j < 12; ++j) { float v = r[12 + j]; if (v > zv) { zv = v; zb = j; } }
    int rb = 0; float rv = r[49];
    #pragma unroll
    for (int j = 1; j < 12; ++j) { float v = r[49 + j]; if (v > rv) { rv = v; rb = j; } }

    const float x_res  = r[24 + xb];
    const float z_res  = r[36 + zb];
    const float y_off  = r[48];
    const float ry_res = r[61 + rb];
    const float hr = r[73], wr = r[74], lr = r[75];

    const float roi0 = sxyz[tid * 3 + 0];
    const float roi1 = sxyz[tid * 3 + 1];
    const float roi2 = sxyz[tid * 3 + 2];

    const float an0 = __ldg(anchor);
    const float an1 = __ldg(anchor + 1);
    const float an2 = __ldg(anchor + 2);

    const float LOC_BIN = 0.5f, HALF = 0.25f, SCOPE = 3.0f;
    const float pos_x = (float)xb * LOC_BIN + HALF - SCOPE + x_res * LOC_BIN;
    const float pos_z = (float)zb * LOC_BIN + HALF - SCOPE + z_res * LOC_BIN;
    const float pos_y = roi1 + y_off;

    const float TWO_PI = 6.28318530717958647692f;
    const float PI_    = 3.14159265358979323846f;
    const float APC    = 0.52359877559829887308f;   // 2*pi/12
    float ry = (float)rb * APC + ry_res * (APC * 0.5f);
    ry = fmodf(ry, TWO_PI);
    if (ry < 0.f) ry += TWO_PI;
    if (ry > PI_) ry -= TWO_PI;

    const float h_ = hr * an0 + an0;
    const float w_ = wr * an1 + an1;
    const float l_ = lr * an2 + an2;

    const float px = pos_x + roi0;
    const float pz = pos_z + roi2;
    const float py = pos_y + h_ * 0.5f;

    const float sc = __ldg(scores + p);

    float4* pp = (float4*)g_props;
    pp[2 * (size_t)p]     = make_float4(px, py, pz, h_);
    pp[2 * (size_t)p + 1] = make_float4(w_, l_, ry, sc);

    unsigned int u = __float_as_uint(sc);
    u ^= (u & 0x80000000u) ? 0xFFFFFFFFu : 0x80000000u;
    g_keys[p] = ~u;              // ascending == descending score
    g_vals[p] = (unsigned int)p;
}

// ---------------- histogram: all 4 pass histograms in one read ----------------
__global__ __launch_bounds__(256) void hist_kernel(const unsigned int* __restrict__ keys)
{
    __shared__ unsigned int h[4][256];
    const int tid = threadIdx.x;
    #pragma unroll
    for (int p = 0; p < 4; ++p) h[p][tid] = 0;
    __syncthreads();
    const size_t base = (size_t)blockIdx.x * 256 * 8;
    #pragma unroll
    for (int k = 0; k < 8; ++k) {
        const unsigned int key = keys[base + k * 256 + tid];
        atomicAdd(&h[0][key & 255u], 1u);
        atomicAdd(&h[1][(key >> 8) & 255u], 1u);
        atomicAdd(&h[2][(key >> 16) & 255u], 1u);
        atomicAdd(&h[3][key >> 24], 1u);
    }
    __syncthreads();
    #pragma unroll
    for (int p = 0; p < 4; ++p) atomicAdd(&g_state.hist[p][tid], h[p][tid]);
}

// ---------------- exclusive scan of the 4 histograms (1 block) ----------------
__global__ __launch_bounds__(256) void scan_kernel()
{
    __shared__ unsigned int s[512];
    const int tid = threadIdx.x;
    for (int p = 0; p < 4; ++p) {
        const unsigned int x = g_state.hist[p][tid];
        s[tid] = 0; s[256 + tid] = x;
        __syncthreads();
        #pragma unroll
        for (int d = 1; d < 256; d <<= 1) {
            const unsigned int v = s[256 + tid] + s[256 + tid - d];
            __syncthreads();
            s[256 + tid] = v;
            __syncthreads();
        }
        g_bin_excl[p][tid] = s[256 + tid] - x;   // exclusive
        __syncthreads();
    }
}

// windowed decoupled lookback: MLP=LBW independent status loads per round.
// col points at status[0][bin]; stride is row stride in words.
__device__ __forceinline__ unsigned int lookback_windowed(
    volatile unsigned int* col, size_t stride, int tile)
{
    unsigned int excl = 0;
    int t = tile - 1;
    bool done = false;
    while (!done) {
        unsigned int w[LBW];
        #pragma unroll
        for (int i = 0; i < LBW; ++i) {                // independent loads (MLP)
            const int tt = t - i;
            w[i] = (tt >= 0) ? col[(size_t)tt * stride] : (FLAG_INC | 0u);
        }
        #pragma unroll
        for (int i = 0; i < LBW; ++i) {                // poll stragglers only
            const int tt = t - i;
            if (tt >= 0) while (w[i] == 0u) w[i] = col[(size_t)tt * stride];
        }
        #pragma unroll
        for (int i = 0; i < LBW; ++i) {
            if (!done) {
                excl += w[i] & VALMASK;
                if (w[i] & FLAG_INC) done = true;
            }
        }
        t -= LBW;
    }
    return excl;
}

// ---------------- custom onesweep pass (stable, pairs) ----------------
template<int SHIFT, int PASS, bool WRITE_KEYS>
__global__ __launch_bounds__(STH) void onesweep_pass(
    const unsigned int* __restrict__ keys_in,
    const unsigned int* __restrict__ vals_in,
    unsigned int* __restrict__ keys_out,
    unsigned int* __restrict__ vals_out)
{
    __shared__ unsigned int s_keys[STILE];       // 16 KB
    __shared__ unsigned int s_vals[STILE];       // 16 KB
    __shared__ unsigned int s_wc[8][256];        // 8 KB
    __shared__ unsigned int s_tile_excl[256];
    __shared__ unsigned int s_gbase[256];
    __shared__ unsigned int s_scan[512];
    __shared__ unsigned int s_tileid;

    const int tid = threadIdx.x, lane = tid & 31, warp = tid >> 5;
    const unsigned FULL = 0xffffffffu;
    const unsigned lt   = (1u << lane) - 1u;

    if (tid == 0) s_tileid = atomicAdd(&g_state.counters[PASS], 1u);
    #pragma unroll
    for (int i = 0; i < 8; ++i) (&s_wc[0][0])[tid + i * 256] = 0;
    __syncthreads();
    const int    tile  = (int)s_tileid;
    const size_t ibase = (size_t)tile * STILE;
    const size_t wbase = ibase + (size_t)warp * WSEG;

    unsigned int key[SIT];
    unsigned short rnk[SIT];
    unsigned int* wc = s_wc[warp];

    // warp-private stable ranking (no block barriers)
    #pragma unroll
    for (int k = 0; k < SIT; ++k) {
        key[k] = keys_in[wbase + k * 32 + lane];
        const unsigned int d     = (key[k] >> SHIFT) & 255u;
        const unsigned int peers = __match_any_sync(FULL, d);
        const unsigned int cnt   = wc[d];
        rnk[k] = (unsigned short)(cnt + __popc(peers & lt));
        if ((peers >> lane) == 1u)
            wc[d] = cnt + __popc(peers);
        __syncwarp();
    }
    __syncthreads();

    // per-digit cross-warp exclusive scan + totals (thread tid owns digit tid)
    unsigned int run = 0;
    #pragma unroll
    for (int w = 0; w < 8; ++w) {
        const unsigned int c = s_wc[w][tid];
        s_wc[w][tid] = run;
        run += c;
    }
    const unsigned int agg = run;

    // publish aggregate early
    if (tile == 0)
        ((volatile unsigned int*)g_state.sort_status[PASS][0])[tid] = FLAG_INC | agg;
    else
        ((volatile unsigned int*)g_state.sort_status[PASS][tile])[tid] = FLAG_AGG | agg;
    __threadfence();

    // intra-tile exclusive scan of digit totals
    s_scan[tid] = 0; s_scan[256 + tid] = agg;
    __syncthreads();
    #pragma unroll
    for (int d = 1; d < 256; d <<= 1) {
        const unsigned int v = s_scan[256 + tid] + s_scan[256 + tid - d];
        __syncthreads();
        s_scan[256 + tid] = v;
        __syncthreads();
    }
    s_tile_excl[tid] = s_scan[256 + tid] - agg;
    __syncthreads();

    // stage into smem grouped by digit; fetch vals from gmem on the fly
    #pragma unroll
    for (int k = 0; k < SIT; ++k) {
        const unsigned int d   = (key[k] >> SHIFT) & 255u;
        const unsigned int pos = s_tile_excl[d] + s_wc[warp][d] + rnk[k];
        s_keys[pos] = key[k];
        s_vals[pos] = vals_in[wbase + k * 32 + lane];
    }

    // windowed decoupled lookback: thread tid owns bin tid
    unsigned int excl = 0;
    if (tile > 0) {
        excl = lookback_windowed(&g_state.sort_status[PASS][0][tid], 256, tile);
        ((volatile unsigned int*)g_state.sort_status[PASS][tile])[tid] = FLAG_INC | (excl + agg);
        __threadfence();
    }
    s_gbase[tid] = g_bin_excl[PASS][tid] + excl - s_tile_excl[tid];
    __syncthreads();

    // coalesced global scatter
    #pragma unroll
    for (int k = 0; k < SIT; ++k) {
        const int j = k * STH + tid;
        const unsigned int kk = s_keys[j];
        const unsigned int d  = (kk >> SHIFT) & 255u;
        const unsigned int dest = s_gbase[d] + j;
        if (WRITE_KEYS) keys_out[dest] = kk;
        vals_out[dest] = s_vals[j];
    }
}

// ------- fused stable 8-way rank (windowed lookback) + gather/scatter -------
__global__ __launch_bounds__(GTH) void rank_gather_kernel(
    const unsigned int* __restrict__ sorted_vals,
    float4* __restrict__ out)
{
    __shared__ unsigned int s_wc[8][8];    // [warp][row]
    __shared__ unsigned int s_excl[8];
    __shared__ unsigned int s_tile;

    const int tid  = threadIdx.x;
    const int lane = tid & 31;
    const int warp = tid >> 5;
    const unsigned FULL = 0xffffffffu;
    const unsigned lt   = (1u << lane) - 1u;

    if (tid == 0) s_tile = atomicAdd(&g_state.counters[4], 1u);
    if (tid < 64) (&s_wc[0][0])[tid] = 0;
    __syncthreads();
    const int    tile  = (int)s_tile;
    const size_t wbase = (size_t)tile * GTILE + (size_t)warp * GSEG;

    unsigned int v[GIT]; unsigned int row[GIT]; unsigned short rnk[GIT];
    unsigned int* wc = s_wc[warp];

    // warp-private stable 8-way ranking (rows interleaved in sorted stream)
    #pragma unroll
    for (int k = 0; k < GIT; ++k) {
        v[k]   = __ldg(sorted_vals + wbase + k * 32 + lane);
        row[k] = v[k] >> 17;
        const unsigned int peers = __match_any_sync(FULL, row[k]);
        const unsigned int cnt   = wc[row[k]];
        rnk[k] = (unsigned short)(cnt + __popc(peers & lt));
        if ((peers >> lane) == 1u)
            wc[row[k]] = cnt + __popc(peers);
        __syncwarp();
    }
    __syncthreads();

    if (tid < 8) {   // thread tid owns row tid
        unsigned int run = 0;
        #pragma unroll
        for (int w = 0; w < 8; ++w) {
            const unsigned int c = s_wc[w][tid];
            s_wc[w][tid] = run;
            run += c;
        }
        const unsigned int agg = run;
        if (tile == 0) {
            ((volatile unsigned int*)g_state.rg_status[0])[tid] = FLAG_INC | agg;
            __threadfence();
            s_excl[tid] = 0;
        } else {
            ((volatile unsigned int*)g_state.rg_status[tile])[tid] = FLAG_AGG | agg;
            __threadfence();
            const unsigned int excl = lookback_windowed(&g_state.rg_status[0][tid], 8, tile);
            ((volatile unsigned int*)g_state.rg_status[tile])[tid] = FLAG_INC | (excl + agg);
            __threadfence();
            s_excl[tid] = excl;
        }
    }
    __syncthreads();

    const float4* pp = (const float4*)g_props;
    #pragma unroll
    for (int k = 0; k < GIT; ++k) {
        const unsigned int src = v[k];
        const unsigned int dst = row[k] * N_ + s_excl[row[k]] + s_wc[warp][row[k]] + rnk[k];
        out[2 * (size_t)dst]     = __ldg(&pp[2 * (size_t)src]);
        out[2 * (size_t)dst + 1] = __ldg(&pp[2 * (size_t)src + 1]);
    }
}

// ---------------- launch ----------------
extern "C" void kernel_launch(void* const* d_in, const int* in_sizes, int n_in,
                              void* d_out, int out_size)
{
    const float* scores = (const float*)d_in[0];
    const float* reg    = (const float*)d_in[1];
    const float* xyz    = (const float*)d_in[2];
    const float* anchor = (const float*)d_in[3];

    void* pst; cudaGetSymbolAddress(&pst, g_state);
    cudaMemsetAsync(pst, 0, sizeof(State));

    decode_kernel<<<M_ / PTS, PTS>>>(scores, reg, xyz, anchor);

    void *pk, *pka, *pv, *pva;
    cudaGetSymbolAddress(&pk,  g_keys);
    cudaGetSymbolAddress(&pka, g_keys_alt);
    cudaGetSymbolAddress(&pv,  g_vals);
    cudaGetSymbolAddress(&pva, g_vals_alt);

    hist_kernel<<<M_ / (256 * 8), 256>>>((const unsigned int*)pk);
    scan_kernel<<<1, 256>>>();

    onesweep_pass< 0, 0, true ><<<SNT, STH>>>((const unsigned int*)pk,  (const unsigned int*)pv,
                                              (unsigned int*)pka, (unsigned int*)pva);
    onesweep_pass< 8, 1, true ><<<SNT, STH>>>((const unsigned int*)pka, (const unsigned int*)pva,
                                              (unsigned int*)pk,  (unsigned int*)pv);
    onesweep_pass<16, 2, true ><<<SNT, STH>>>((const unsigned int*)pk,  (const unsigned int*)pv,
                                              (unsigned int*)pka, (unsigned int*)pva);
    onesweep_pass<24, 3, false><<<SNT, STH>>>((const unsigned int*)pka, (const unsigned int*)pva,
                                              (unsigned int*)pk,  (unsigned int*)pv);

    rank_gather_kernel<<<NTILES, GTH>>>((const unsigned int*)pv, (float4*)d_out);
}

// round 7
// speedup vs baseline: 1.1246x; 1.0334x over previous
#include <cuda_runtime.h>
#include <cstdint>

// Problem constants (from reference setup_inputs)
#define B_  8
#define N_  131072            // 2^17
#define M_  (B_ * N_)         // 1048576 points
#define C_  76
#define PTS 128               // points per decode block

// radix sort config
#define STH   256             // threads per sort tile (8 warps)
#define SIT   16              // items per thread
#define STILE (STH * SIT)     // 4096 items per tile
#define SNT   (M_ / STILE)    // 256 tiles per pass
#define WSEG  (32 * SIT)      // 512 contiguous items per warp

// rank+gather tiling
#define GTH    256
#define GIT    8
#define GTILE  (GTH * GIT)    // 2048
#define NTILES (M_ / GTILE)   // 512
#define GSEG   (32 * GIT)     // 256 contiguous items per warp

#define FLAG_AGG (1u << 30)
#define FLAG_INC (2u << 30)
#define VALMASK  ((1u << 30) - 1u)
#define LBW      16

#define FULLM 0xffffffffu

// ---------------- device scratch (no allocation allowed) ----------------
struct State {                                   // zeroed once per launch (17 KB)
    unsigned int counters[8];                    // [4]=rank_gather tile counter
    unsigned int hist[4][256];                   // global per-pass histograms
    unsigned int rg_status[NTILES][8];           // rank_gather lookback
};
__device__ State        g_state;
__device__ unsigned int g_bin_excl[4][256];      // global digit offsets (overwritten)
__device__ unsigned int g_tp[256][SNT];          // per-digit tile counts -> prefix (overwritten per pass)
__device__ float        g_props[(size_t)M_ * 8]; // 32 MB
__device__ unsigned int g_keys[M_];
__device__ unsigned int g_keys_alt[M_];
__device__ unsigned int g_vals[M_];
__device__ unsigned int g_vals_alt[M_];

// ---------------- decode: thread per point, smem-staged ----------------
__global__ __launch_bounds__(PTS) void decode_kernel(
    const float* __restrict__ scores,
    const float* __restrict__ reg,
    const float* __restrict__ xyz,
    const float* __restrict__ anchor)
{
    __shared__ float s[PTS * 77];
    __shared__ float sxyz[PTS * 3];

    const int tid  = threadIdx.x;
    const int base = blockIdx.x * PTS;

    const float* gsrc = reg + (size_t)base * C_;
    #pragma unroll
    for (int k = 0; k < C_; ++k) {
        const int i = tid + k * PTS;
        const int p = i / C_;
        const int c = i - p * C_;
        s[p * 77 + c] = gsrc[i];
    }
    #pragma unroll
    for (int k = 0; k < 3; ++k)
        sxyz[tid + k * PTS] = xyz[(size_t)base * 3 + tid + k * PTS];
    __syncthreads();

    const int    p = base + tid;
    const float* r = s + tid * 77;

    int xb = 0; float xv = r[0];
    #pragma unroll
    for (int j = 1; j < 12; ++j) { float v = r[j];      if (v > xv) { xv = v; xb = j; } }
    int zb = 0; float zv = r[12];
    #pragma unroll
    for (int j = 1; j < 12; ++j) { float v = r[12 + j]; if (v > zv) { zv = v; zb = j; } }
    int rb = 0; float rv = r[49];
    #pragma unroll
    for (int j = 1; j < 12; ++j) { float v = r[49 + j]; if (v > rv) { rv = v; rb = j; } }

    const float x_res  = r[24 + xb];
    const float z_res  = r[36 + zb];
    const float y_off  = r[48];
    const float ry_res = r[61 + rb];
    const float hr = r[73], wr = r[74], lr = r[75];

    const float roi0 = sxyz[tid * 3 + 0];
    const float roi1 = sxyz[tid * 3 + 1];
    const float roi2 = sxyz[tid * 3 + 2];

    const float an0 = __ldg(anchor);
    const float an1 = __ldg(anchor + 1);
    const float an2 = __ldg(anchor + 2);

    const float LOC_BIN = 0.5f, HALF = 0.25f, SCOPE = 3.0f;
    const float pos_x = (float)xb * LOC_BIN + HALF - SCOPE + x_res * LOC_BIN;
    const float pos_z = (float)zb * LOC_BIN + HALF - SCOPE + z_res * LOC_BIN;
    const float pos_y = roi1 + y_off;

    const float TWO_PI = 6.28318530717958647692f;
    const float PI_    = 3.14159265358979323846f;
    const float APC    = 0.52359877559829887308f;   // 2*pi/12
    float ry = (float)rb * APC + ry_res * (APC * 0.5f);
    ry = fmodf(ry, TWO_PI);
    if (ry < 0.f) ry += TWO_PI;
    if (ry > PI_) ry -= TWO_PI;

    const float h_ = hr * an0 + an0;
    const float w_ = wr * an1 + an1;
    const float l_ = lr * an2 + an2;

    const float px = pos_x + roi0;
    const float pz = pos_z + roi2;
    const float py = pos_y + h_ * 0.5f;

    const float sc = __ldg(scores + p);

    float4* pp = (float4*)g_props;
    pp[2 * (size_t)p]     = make_float4(px, py, pz, h_);
    pp[2 * (size_t)p + 1] = make_float4(w_, l_, ry, sc);

    unsigned int u = __float_as_uint(sc);
    u ^= (u & 0x80000000u) ? 0xFFFFFFFFu : 0x80000000u;
    g_keys[p] = ~u;              // ascending == descending score
    g_vals[p] = (unsigned int)p;
}

// ---- global hist (all 4 passes) + pass-0 tile hist (block == sort tile) ----
__global__ __launch_bounds__(STH) void hist_kernel(const unsigned int* __restrict__ keys)
{
    __shared__ unsigned int h[4][256];
    const int tid = threadIdx.x;
    #pragma unroll
    for (int p = 0; p < 4; ++p) h[p][tid] = 0;
    __syncthreads();
    const size_t base = (size_t)blockIdx.x * STILE;
    #pragma unroll
    for (int k = 0; k < SIT; ++k) {
        const unsigned int key = keys[base + k * STH + tid];
        atomicAdd(&h[0][key & 255u], 1u);
        atomicAdd(&h[1][(key >> 8) & 255u], 1u);
        atomicAdd(&h[2][(key >> 16) & 255u], 1u);
        atomicAdd(&h[3][key >> 24], 1u);
    }
    __syncthreads();
    #pragma unroll
    for (int p = 0; p < 4; ++p) atomicAdd(&g_state.hist[p][tid], h[p][tid]);
    g_tp[tid][blockIdx.x] = h[0][tid];          // pass-0 tile histogram
}

// ---- per-pass tile histogram (for passes 1..3) ----
template<int SHIFT>
__global__ __launch_bounds__(STH) void count_kernel(const unsigned int* __restrict__ keys)
{
    __shared__ unsigned int h[256];
    const int tid = threadIdx.x;
    h[tid] = 0;
    __syncthreads();
    const size_t base = (size_t)blockIdx.x * STILE;
    #pragma unroll
    for (int k = 0; k < SIT; ++k) {
        const unsigned int key = keys[base + k * STH + tid];
        atomicAdd(&h[(key >> SHIFT) & 255u], 1u);
    }
    __syncthreads();
    g_tp[tid][blockIdx.x] = h[tid];
}

// shuffle-based exclusive scan over 256 values (one per thread); returns excl
__device__ __forceinline__ unsigned int block_excl_scan_256(
    unsigned int x, unsigned int* s_warp, int lane, int warp)
{
    unsigned int v = x;
    #pragma unroll
    for (int d = 1; d < 32; d <<= 1) {
        unsigned int n = __shfl_up_sync(FULLM, v, d);
        if (lane >= d) v += n;
    }
    if (lane == 31) s_warp[warp] = v;
    __syncthreads();
    if (warp == 0) {
        unsigned int w = (lane < 8) ? s_warp[lane] : 0u;
        #pragma unroll
        for (int d = 1; d < 8; d <<= 1) {
            unsigned int n = __shfl_up_sync(FULLM, w, d);
            if (lane >= d) w += n;
        }
        if (lane < 8) s_warp[lane] = w;
    }
    __syncthreads();
    const unsigned int base = (warp > 0) ? s_warp[warp - 1] : 0u;
    return base + v - x;
}

// ---- exclusive scan of the 4 global histograms (1 block) ----
__global__ __launch_bounds__(256) void scan_kernel()
{
    __shared__ unsigned int s_warp[8];
    const int tid = threadIdx.x, lane = tid & 31, warp = tid >> 5;
    for (int p = 0; p < 4; ++p) {
        const unsigned int x = g_state.hist[p][tid];
        g_bin_excl[p][tid] = block_excl_scan_256(x, s_warp, lane, warp);
        __syncthreads();
    }
}

// ---- per-digit exclusive scan over tiles: g_tp[d][*] counts -> prefixes ----
__global__ __launch_bounds__(SNT) void tile_prefix_kernel()
{
    __shared__ unsigned int s_warp[8];
    const int d = blockIdx.x, t = threadIdx.x;
    const int lane = t & 31, warp = t >> 5;
    const unsigned int x = g_tp[d][t];
    const unsigned int e = block_excl_scan_256(x, s_warp, lane, warp);
    g_tp[d][t] = e;
}

// ---------------- scatter pass (stable, pairs, NO lookback) ----------------
template<int SHIFT, int PASS, bool WRITE_KEYS>
__global__ __launch_bounds__(STH) void scatter_pass(
    const unsigned int* __restrict__ keys_in,
    const unsigned int* __restrict__ vals_in,
    unsigned int* __restrict__ keys_out,
    unsigned int* __restrict__ vals_out)
{
    __shared__ unsigned int s_keys[STILE];       // 16 KB
    __shared__ unsigned int s_vals[STILE];       // 16 KB
    __shared__ unsigned int s_wc[8][256];        // 8 KB
    __shared__ unsigned int s_tile_excl[256];
    __shared__ unsigned int s_gbase[256];
    __shared__ unsigned int s_warp[8];

    const int tid = threadIdx.x, lane = tid & 31, warp = tid >> 5;
    const unsigned lt = (1u << lane) - 1u;

    const int    tile  = blockIdx.x;
    const size_t wbase = (size_t)tile * STILE + (size_t)warp * WSEG;

    #pragma unroll
    for (int i = 0; i < 8; ++i) (&s_wc[0][0])[tid + i * 256] = 0;
    __syncthreads();

    unsigned int key[SIT];
    unsigned short rnk[SIT];
    unsigned int* wc = s_wc[warp];

    // warp-private stable ranking (no block barriers)
    #pragma unroll
    for (int k = 0; k < SIT; ++k) {
        key[k] = keys_in[wbase + k * 32 + lane];
        const unsigned int d     = (key[k] >> SHIFT) & 255u;
        const unsigned int peers = __match_any_sync(FULLM, d);
        const unsigned int cnt   = wc[d];
        rnk[k] = (unsigned short)(cnt + __popc(peers & lt));
        if ((peers >> lane) == 1u)
            wc[d] = cnt + __popc(peers);
        __syncwarp();
    }
    __syncthreads();

    // cross-warp exclusive scan per digit (thread tid owns digit tid)
    unsigned int run = 0;
    #pragma unroll
    for (int w = 0; w < 8; ++w) {
        const unsigned int c = s_wc[w][tid];
        s_wc[w][tid] = run;
        run += c;
    }
    const unsigned int agg = run;

    // intra-tile digit base + precomputed global base (no lookback!)
    const unsigned int texcl = block_excl_scan_256(agg, s_warp, lane, warp);
    s_tile_excl[tid] = texcl;
    s_gbase[tid] = g_bin_excl[PASS][tid] + g_tp[tid][tile] - texcl;
    __syncthreads();

    // stage into smem grouped by digit; fetch vals from gmem on the fly
    #pragma unroll
    for (int k = 0; k < SIT; ++k) {
        const unsigned int d   = (key[k] >> SHIFT) & 255u;
        const unsigned int pos = s_tile_excl[d] + s_wc[warp][d] + rnk[k];
        s_keys[pos] = key[k];
        s_vals[pos] = vals_in[wbase + k * 32 + lane];
    }
    __syncthreads();

    // coalesced global scatter
    #pragma unroll
    for (int k = 0; k < SIT; ++k) {
        const int j = k * STH + tid;
        const unsigned int kk = s_keys[j];
        const unsigned int d  = (kk >> SHIFT) & 255u;
        const unsigned int dest = s_gbase[d] + j;
        if (WRITE_KEYS) keys_out[dest] = kk;
        vals_out[dest] = s_vals[j];
    }
}

// windowed decoupled lookback (rank_gather only; 8-bin state)
__device__ __forceinline__ unsigned int lookback_windowed(
    volatile unsigned int* col, size_t stride, int tile)
{
    unsigned int excl = 0;
    int t = tile - 1;
    bool done = false;
    while (!done) {
        unsigned int w[LBW];
        #pragma unroll
        for (int i = 0; i < LBW; ++i) {
            const int tt = t - i;
            w[i] = (tt >= 0) ? col[(size_t)tt * stride] : (FLAG_INC | 0u);
        }
        #pragma unroll
        for (int i = 0; i < LBW; ++i) {
            const int tt = t - i;
            if (tt >= 0) while (w[i] == 0u) w[i] = col[(size_t)tt * stride];
        }
        #pragma unroll
        for (int i = 0; i < LBW; ++i) {
            if (!done) {
                excl += w[i] & VALMASK;
                if (w[i] & FLAG_INC) done = true;
            }
        }
        t -= LBW;
    }
    return excl;
}

// ------- fused stable 8-way rank (windowed lookback) + gather/scatter -------
__global__ __launch_bounds__(GTH) void rank_gather_kernel(
    const unsigned int* __restrict__ sorted_vals,
    float4* __restrict__ out)
{
    __shared__ unsigned int s_wc[8][8];
    __shared__ unsigned int s_excl[8];
    __shared__ unsigned int s_tile;

    const int tid  = threadIdx.x;
    const int lane = tid & 31;
    const int warp = tid >> 5;
    const unsigned lt = (1u << lane) - 1u;

    if (tid == 0) s_tile = atomicAdd(&g_state.counters[4], 1u);
    if (tid < 64) (&s_wc[0][0])[tid] = 0;
    __syncthreads();
    const int    tile  = (int)s_tile;
    const size_t wbase = (size_t)tile * GTILE + (size_t)warp * GSEG;

    unsigned int v[GIT]; unsigned int row[GIT]; unsigned short rnk[GIT];
    unsigned int* wc = s_wc[warp];

    #pragma unroll
    for (int k = 0; k < GIT; ++k) {
        v[k]   = __ldg(sorted_vals + wbase + k * 32 + lane);
        row[k] = v[k] >> 17;
        const unsigned int peers = __match_any_sync(FULLM, row[k]);
        const unsigned int cnt   = wc[row[k]];
        rnk[k] = (unsigned short)(cnt + __popc(peers & lt));
        if ((peers >> lane) == 1u)
            wc[row[k]] = cnt + __popc(peers);
        __syncwarp();
    }
    __syncthreads();

    if (tid < 8) {
        unsigned int run = 0;
        #pragma unroll
        for (int w = 0; w < 8; ++w) {
            const unsigned int c = s_wc[w][tid];
            s_wc[w][tid] = run;
            run += c;
        }
        const unsigned int agg = run;
        if (tile == 0) {
            ((volatile unsigned int*)g_state.rg_status[0])[tid] = FLAG_INC | agg;
            __threadfence();
            s_excl[tid] = 0;
        } else {
            ((volatile unsigned int*)g_state.rg_status[tile])[tid] = FLAG_AGG | agg;
            __threadfence();
            const unsigned int excl = lookback_windowed(&g_state.rg_status[0][tid], 8, tile);
            ((volatile unsigned int*)g_state.rg_status[tile])[tid] = FLAG_INC | (excl + agg);
            __threadfence();
            s_excl[tid] = excl;
        }
    }
    __syncthreads();

    const float4* pp = (const float4*)g_props;
    #pragma unroll
    for (int k = 0; k < GIT; ++k) {
        const unsigned int src = v[k];
        const unsigned int dst = row[k] * N_ + s_excl[row[k]] + s_wc[warp][row[k]] + rnk[k];
        out[2 * (size_t)dst]     = __ldg(&pp[2 * (size_t)src]);
        out[2 * (size_t)dst + 1] = __ldg(&pp[2 * (size_t)src + 1]);
    }
}

// ---------------- launch ----------------
extern "C" void kernel_launch(void* const* d_in, const int* in_sizes, int n_in,
                              void* d_out, int out_size)
{
    const float* scores = (const float*)d_in[0];
    const float* reg    = (const float*)d_in[1];
    const float* xyz    = (const float*)d_in[2];
    const float* anchor = (const float*)d_in[3];

    void* pst; cudaGetSymbolAddress(&pst, g_state);
    cudaMemsetAsync(pst, 0, sizeof(State));

    decode_kernel<<<M_ / PTS, PTS>>>(scores, reg, xyz, anchor);

    void *pk, *pka, *pv, *pva;
    cudaGetSymbolAddress(&pk,  g_keys);
    cudaGetSymbolAddress(&pka, g_keys_alt);
    cudaGetSymbolAddress(&pv,  g_vals);
    cudaGetSymbolAddress(&pva, g_vals_alt);

    const unsigned int* K0 = (const unsigned int*)pk;
    const unsigned int* V0 = (const unsigned int*)pv;
    unsigned int* K1 = (unsigned int*)pka;
    unsigned int* V1 = (unsigned int*)pva;

    hist_kernel<<<SNT, STH>>>(K0);               // global hists + pass0 tile hist
    scan_kernel<<<1, 256>>>();

    // pass 0: K0 -> K1
    tile_prefix_kernel<<<256, SNT>>>();
    scatter_pass< 0, 0, true ><<<SNT, STH>>>(K0, V0, K1, V1);

    // pass 1: K1 -> K0
    count_kernel< 8><<<SNT, STH>>>(K1);
    tile_prefix_kernel<<<256, SNT>>>();
    scatter_pass< 8, 1, true ><<<SNT, STH>>>(K1, V1, (unsigned int*)pk, (unsigned int*)pv);

    // pass 2: K0 -> K1
    count_kernel<16><<<SNT, STH>>>(K0);
    tile_prefix_kernel<<<256, SNT>>>();
    scatter_pass<16, 2, true ><<<SNT, STH>>>(K0, V0, K1, V1);

    // pass 3: K1 -> K0 (vals only)
    count_kernel<24><<<SNT, STH>>>(K1);
    tile_prefix_kernel<<<256, SNT>>>();
    scatter_pass<24, 3, false><<<SNT, STH>>>(K1, V1, (unsigned int*)pk, (unsigned int*)pv);

    rank_gather_kernel<<<NTILES, GTH>>>(V0, (float4*)d_out);
}